// round 1
// baseline (speedup 1.0000x reference)
#include <cuda_runtime.h>
#include <math.h>

// Shapes (fixed for this problem)
#define C_FULL 1024
#define C_HALF 512
#define HW     4096
#define KLOG   2048   // HW/2, contraction dim of logit GEMMs

// Scratch (device globals -- no runtime allocation allowed)
__device__ float g_q [C_HALF * HW];   // conv_q(x_m)  [512,4096] == reshaped [1024,2048]
__device__ float g_kf[C_HALF * HW];   // conv_k1(x_f)
__device__ float g_kl[C_HALF * HW];   // conv_k2(x_l)
__device__ float g_v [C_FULL * HW];   // conv_v(x_m)  [1024,4096]
__device__ float g_lf[C_FULL * C_FULL];
__device__ float g_ll[C_FULL * C_FULL];
__device__ float g_s [C_FULL * C_FULL];  // softmax(lf)+softmax(ll)

// ---------------------------------------------------------------------------
// Generic fp32 tiled GEMM, 128x128 tile, BK=16, 256 threads, 8x8 per thread.
// MODE 0: C = A[M,K] @ B[K,N] + bias[M]           (conv1x1)
// MODE 1: C = A[M,K] @ B[N,K]^T                   (logits, NT)
// MODE 2: C = gamma * (A @ B) + 0.5*(xf + xl)     (final, NN)
// All dims are multiples of the tile sizes -- no bounds checks.
// ---------------------------------------------------------------------------
template<int MODE>
__global__ __launch_bounds__(256)
void sgemm_kernel(const float* __restrict__ A, const float* __restrict__ B,
                  float* __restrict__ C, int M, int N, int K,
                  const float* __restrict__ bias,
                  const float* __restrict__ xf, const float* __restrict__ xl,
                  const float* __restrict__ gpt)
{
    __shared__ float As[16][128];
    __shared__ float Bs[16][128];

    const int tid = threadIdx.x;
    const int tx  = tid & 15;        // 0..15  -> n
    const int ty  = tid >> 4;        // 0..15  -> m
    const int bm0 = blockIdx.y * 128;
    const int bn0 = blockIdx.x * 128;

    float acc[8][8];
    #pragma unroll
    for (int i = 0; i < 8; i++)
        #pragma unroll
        for (int j = 0; j < 8; j++) acc[i][j] = 0.0f;

    for (int kt = 0; kt < K; kt += 16) {
        // ---- load A tile (128 rows x 16 K), store transposed As[k][m] ----
        #pragma unroll
        for (int it = 0; it < 2; it++) {
            int i2 = tid + it * 256;           // 0..511
            int r  = i2 >> 2;                  // row 0..127
            int kv = (i2 & 3) << 2;            // K offset 0,4,8,12
            float4 t = *(const float4*)&A[(size_t)(bm0 + r) * K + kt + kv];
            As[kv + 0][r] = t.x;
            As[kv + 1][r] = t.y;
            As[kv + 2][r] = t.z;
            As[kv + 3][r] = t.w;
        }
        // ---- load B tile ----
        if (MODE == 1) {
            // B is [N,K] row-major: same pattern as A, transposed into Bs[k][n]
            #pragma unroll
            for (int it = 0; it < 2; it++) {
                int i2 = tid + it * 256;
                int r  = i2 >> 2;              // n 0..127
                int kv = (i2 & 3) << 2;
                float4 t = *(const float4*)&B[(size_t)(bn0 + r) * K + kt + kv];
                Bs[kv + 0][r] = t.x;
                Bs[kv + 1][r] = t.y;
                Bs[kv + 2][r] = t.z;
                Bs[kv + 3][r] = t.w;
            }
        } else {
            // B is [K,N] row-major: coalesced float4 copy
            #pragma unroll
            for (int it = 0; it < 2; it++) {
                int i2 = tid + it * 256;
                int r  = i2 >> 5;              // k 0..15
                int c4 = (i2 & 31) << 2;       // n offset
                *(float4*)&Bs[r][c4] =
                    *(const float4*)&B[(size_t)(kt + r) * N + bn0 + c4];
            }
        }
        __syncthreads();

        // ---- compute ----
        #pragma unroll
        for (int kk = 0; kk < 16; kk++) {
            float4 a0 = *(const float4*)&As[kk][ty * 8];
            float4 a1 = *(const float4*)&As[kk][ty * 8 + 4];
            float4 b0 = *(const float4*)&Bs[kk][tx * 8];
            float4 b1 = *(const float4*)&Bs[kk][tx * 8 + 4];
            float a[8] = {a0.x, a0.y, a0.z, a0.w, a1.x, a1.y, a1.z, a1.w};
            float b[8] = {b0.x, b0.y, b0.z, b0.w, b1.x, b1.y, b1.z, b1.w};
            #pragma unroll
            for (int i = 0; i < 8; i++)
                #pragma unroll
                for (int j = 0; j < 8; j++)
                    acc[i][j] = fmaf(a[i], b[j], acc[i][j]);
        }
        __syncthreads();
    }

    // ---- epilogue ----
    const int m0 = bm0 + ty * 8;
    const int n0 = bn0 + tx * 8;
    float g = (MODE == 2) ? gpt[0] : 0.0f;
    #pragma unroll
    for (int i = 0; i < 8; i++) {
        int m = m0 + i;
        float bi = (MODE == 0) ? bias[m] : 0.0f;
        #pragma unroll
        for (int j = 0; j < 8; j++) {
            size_t idx = (size_t)m * N + (n0 + j);
            float r;
            if (MODE == 0)      r = acc[i][j] + bi;
            else if (MODE == 1) r = acc[i][j];
            else                r = g * acc[i][j] + 0.5f * (xf[idx] + xl[idx]);
            C[idx] = r;
        }
    }
}

// ---------------------------------------------------------------------------
// Fused dual softmax: S[row] = softmax(LF[row]) + softmax(LL[row]), rows of 1024.
// One block (256 threads) per row.
// ---------------------------------------------------------------------------
__global__ __launch_bounds__(256)
void softmax_sum_kernel(const float* __restrict__ LF, const float* __restrict__ LL,
                        float* __restrict__ S)
{
    const int row = blockIdx.x;
    const int tid = threadIdx.x;
    __shared__ float red[256];

    const float* pf = LF + (size_t)row * 1024;
    const float* pl = LL + (size_t)row * 1024;

    float vf[4], vl[4];
    #pragma unroll
    for (int k = 0; k < 4; k++) {
        vf[k] = pf[tid + 256 * k];
        vl[k] = pl[tid + 256 * k];
    }

    // --- softmax F ---
    float m = fmaxf(fmaxf(vf[0], vf[1]), fmaxf(vf[2], vf[3]));
    red[tid] = m; __syncthreads();
    for (int s = 128; s > 0; s >>= 1) {
        if (tid < s) red[tid] = fmaxf(red[tid], red[tid + s]);
        __syncthreads();
    }
    float Mf = red[0]; __syncthreads();

    float ef[4], sf = 0.0f;
    #pragma unroll
    for (int k = 0; k < 4; k++) { ef[k] = expf(vf[k] - Mf); sf += ef[k]; }
    red[tid] = sf; __syncthreads();
    for (int s = 128; s > 0; s >>= 1) {
        if (tid < s) red[tid] += red[tid + s];
        __syncthreads();
    }
    float Sf = red[0]; __syncthreads();

    // --- softmax L ---
    m = fmaxf(fmaxf(vl[0], vl[1]), fmaxf(vl[2], vl[3]));
    red[tid] = m; __syncthreads();
    for (int s = 128; s > 0; s >>= 1) {
        if (tid < s) red[tid] = fmaxf(red[tid], red[tid + s]);
        __syncthreads();
    }
    float Ml = red[0]; __syncthreads();

    float el[4], sl = 0.0f;
    #pragma unroll
    for (int k = 0; k < 4; k++) { el[k] = expf(vl[k] - Ml); sl += el[k]; }
    red[tid] = sl; __syncthreads();
    for (int s = 128; s > 0; s >>= 1) {
        if (tid < s) red[tid] += red[tid + s];
        __syncthreads();
    }
    float Sl = red[0];

    float invf = 1.0f / Sf;
    float invl = 1.0f / Sl;
    #pragma unroll
    for (int k = 0; k < 4; k++)
        S[(size_t)row * 1024 + tid + 256 * k] = ef[k] * invf + el[k] * invl;
}

// ---------------------------------------------------------------------------
extern "C" void kernel_launch(void* const* d_in, const int* in_sizes, int n_in,
                              void* d_out, int out_size)
{
    (void)in_sizes; (void)n_in; (void)out_size;
    const float* x_f   = (const float*)d_in[0];
    const float* x_m   = (const float*)d_in[1];
    const float* x_l   = (const float*)d_in[2];
    const float* Wq    = (const float*)d_in[3];
    const float* bq    = (const float*)d_in[4];
    const float* Wk1   = (const float*)d_in[5];
    const float* bk1   = (const float*)d_in[6];
    const float* Wk2   = (const float*)d_in[7];
    const float* bk2   = (const float*)d_in[8];
    const float* Wv    = (const float*)d_in[9];
    const float* bv    = (const float*)d_in[10];
    const float* gamma = (const float*)d_in[11];
    float* out = (float*)d_out;

    float *q, *kf, *kl, *v, *lf, *ll, *s;
    cudaGetSymbolAddress((void**)&q,  g_q);
    cudaGetSymbolAddress((void**)&kf, g_kf);
    cudaGetSymbolAddress((void**)&kl, g_kl);
    cudaGetSymbolAddress((void**)&v,  g_v);
    cudaGetSymbolAddress((void**)&lf, g_lf);
    cudaGetSymbolAddress((void**)&ll, g_ll);
    cudaGetSymbolAddress((void**)&s,  g_s);

    dim3 blk(256);

    // conv1x1 GEMMs: W[Cout,C] @ X[C,HW] + b
    sgemm_kernel<0><<<dim3(HW / 128, C_HALF / 128), blk>>>(
        Wq,  x_m, q,  C_HALF, HW, C_FULL, bq,  nullptr, nullptr, nullptr);
    sgemm_kernel<0><<<dim3(HW / 128, C_HALF / 128), blk>>>(
        Wk1, x_f, kf, C_HALF, HW, C_FULL, bk1, nullptr, nullptr, nullptr);
    sgemm_kernel<0><<<dim3(HW / 128, C_HALF / 128), blk>>>(
        Wk2, x_l, kl, C_HALF, HW, C_FULL, bk2, nullptr, nullptr, nullptr);
    sgemm_kernel<0><<<dim3(HW / 128, C_FULL / 128), blk>>>(
        Wv,  x_m, v,  C_FULL, HW, C_FULL, bv,  nullptr, nullptr, nullptr);

    // logits: [1024,2048] @ [1024,2048]^T  (reshape of conv outputs is a free
    // reinterpret: row-major [512,4096] flat == row-major [1024,2048] flat)
    sgemm_kernel<1><<<dim3(C_FULL / 128, C_FULL / 128), blk>>>(
        kf, q, lf, C_FULL, C_FULL, KLOG, nullptr, nullptr, nullptr, nullptr);
    sgemm_kernel<1><<<dim3(C_FULL / 128, C_FULL / 128), blk>>>(
        kl, q, ll, C_FULL, C_FULL, KLOG, nullptr, nullptr, nullptr, nullptr);

    // S = softmax(lf) + softmax(ll)   (att_f@v + att_l@v == (att_f+att_l)@v)
    softmax_sum_kernel<<<C_FULL, blk>>>(lf, ll, s);

    // out = gamma * (S @ V) + 0.5*(x_f + x_l)
    sgemm_kernel<2><<<dim3(HW / 128, C_FULL / 128), blk>>>(
        s, v, out, C_FULL, HW, C_FULL, nullptr, x_f, x_l, gamma);
}

// round 3
// speedup vs baseline: 2.8130x; 2.8130x over previous
#include <cuda_runtime.h>
#include <cuda_fp16.h>
#include <math.h>
#include <stdint.h>

#define C_FULL 1024
#define C_HALF 512
#define HW     4096
#define KLOG   2048

// ---------------- scratch (device globals; no runtime allocation) ----------
__device__ __half g_xTm_h[HW*C_FULL], g_xTm_l[HW*C_FULL];
__device__ __half g_xTf_h[HW*C_FULL], g_xTf_l[HW*C_FULL];
__device__ __half g_xTl_h[HW*C_FULL], g_xTl_l[HW*C_FULL];
__device__ __half g_Wq_h [C_HALF*C_FULL], g_Wq_l [C_HALF*C_FULL];
__device__ __half g_Wk1_h[C_HALF*C_FULL], g_Wk1_l[C_HALF*C_FULL];
__device__ __half g_Wk2_h[C_HALF*C_FULL], g_Wk2_l[C_HALF*C_FULL];
__device__ __half g_Wv_h [C_FULL*C_FULL], g_Wv_l [C_FULL*C_FULL];
__device__ __half g_q_h [C_HALF*HW], g_q_l [C_HALF*HW];
__device__ __half g_kf_h[C_HALF*HW], g_kf_l[C_HALF*HW];
__device__ __half g_kl_h[C_HALF*HW], g_kl_l[C_HALF*HW];
__device__ __half g_vT_h[HW*C_FULL], g_vT_l[HW*C_FULL];
__device__ float  g_lf[C_FULL*C_FULL], g_ll[C_FULL*C_FULL];
__device__ __half g_S_h[C_FULL*C_FULL], g_S_l[C_FULL*C_FULL];

// ---------------- helpers ---------------------------------------------------
__device__ __forceinline__ uint32_t smem_u32(const void* p) {
    uint32_t r;
    asm("{ .reg .u64 t; cvta.to.shared.u64 t, %1; cvt.u32.u64 %0, t; }"
        : "=r"(r) : "l"(p));
    return r;
}
__device__ __forceinline__ void cp_async16(uint32_t dst, const void* src) {
    asm volatile("cp.async.cg.shared.global [%0], [%1], 16;" :: "r"(dst), "l"(src));
}
__device__ __forceinline__ void cp_commit() { asm volatile("cp.async.commit_group;"); }

__device__ __forceinline__ void ldsm4(uint32_t addr, uint32_t& r0, uint32_t& r1,
                                      uint32_t& r2, uint32_t& r3) {
    asm volatile("ldmatrix.sync.aligned.m8n8.x4.shared.b16 {%0,%1,%2,%3}, [%4];"
                 : "=r"(r0), "=r"(r1), "=r"(r2), "=r"(r3) : "r"(addr));
}
__device__ __forceinline__ void hmma(float* d, const uint32_t* a, const uint32_t* b) {
    asm volatile("mma.sync.aligned.m16n8k16.row.col.f32.f16.f16.f32 "
                 "{%0,%1,%2,%3}, {%4,%5,%6,%7}, {%8,%9}, {%0,%1,%2,%3};"
                 : "+f"(d[0]), "+f"(d[1]), "+f"(d[2]), "+f"(d[3])
                 : "r"(a[0]), "r"(a[1]), "r"(a[2]), "r"(a[3]),
                   "r"(b[0]), "r"(b[1]));
}

// ---------------- GEMM: D = A @ B^T via 3x fp16-split HMMA ------------------
// A: [M,K] row-major hi/lo.  B: [N,K] row-major hi/lo. K % 32 == 0.
// MODE 0: split-store (D + bias[m]) -> Ch/Cl      (convs q/kf/kl, z-batched)
// MODE 1: split-store (D + bias[n]) -> Ch/Cl      (conv vT)
// MODE 2: fp32 store D -> Cf                      (logits, z-batched)
// MODE 3: fp32 store gamma*D + 0.5*(xf+xl) -> Cf  (final)
struct GemmBatch {
    const __half* Ah[3]; const __half* Al[3];
    const __half* Bh[3]; const __half* Bl[3];
    float* Cf[3]; __half* Ch[3]; __half* Cl[3];
    const float* bias[3];
};

#define BM 128
#define BN 128
#define BK 32
#define TSTRIDE 40                           // halves per smem tile row
#define TILE_HALFS (128 * TSTRIDE)
#define TILE_BYTES (TILE_HALFS * 2)          // 10240
#define STAGE_BYTES (4 * TILE_BYTES)         // 40960
#define GEMM_SMEM (2 * STAGE_BYTES)          // 81920

template<int MODE>
__global__ __launch_bounds__(256, 1)
void mma_gemm(GemmBatch P, int M, int N, int K,
              const float* __restrict__ xf, const float* __restrict__ xl,
              const float* __restrict__ gpt)
{
    extern __shared__ __half sm[];
    const int z = blockIdx.z;
    const __half* __restrict__ Ah = P.Ah[z];
    const __half* __restrict__ Al = P.Al[z];
    const __half* __restrict__ Bh = P.Bh[z];
    const __half* __restrict__ Bl = P.Bl[z];

    const int tid  = threadIdx.x;
    const int lane = tid & 31, wid = tid >> 5;
    const int warp_m = wid & 3, warp_n = wid >> 2;       // 4 x 2 warp grid
    const int bm0 = blockIdx.y * BM, bn0 = blockIdx.x * BN;
    const uint32_t su = smem_u32(sm);

    float acc[2][8][4];
    #pragma unroll
    for (int i = 0; i < 2; i++)
        #pragma unroll
        for (int j = 0; j < 8; j++)
            #pragma unroll
            for (int k = 0; k < 4; k++) acc[i][j][k] = 0.0f;

#define LOAD_STAGE(s, kt) do {                                                \
    const uint32_t sbase_ = su + (uint32_t)(s) * STAGE_BYTES;                 \
    const size_t acol_ = (size_t)(kt) * BK;                                   \
    _Pragma("unroll")                                                         \
    for (int it_ = 0; it_ < 2; it_++) {                                       \
        const int c_ = tid + it_ * 256;                                       \
        const int row_ = c_ >> 2;                                             \
        const int kc_ = (c_ & 3) * 8;                                         \
        const uint32_t off_ = (uint32_t)(row_ * TSTRIDE + kc_) * 2;           \
        const size_t ga_ = (size_t)(bm0 + row_) * K + acol_ + kc_;            \
        const size_t gb_ = (size_t)(bn0 + row_) * K + acol_ + kc_;            \
        cp_async16(sbase_ + 0 * TILE_BYTES + off_, Ah + ga_);                 \
        cp_async16(sbase_ + 1 * TILE_BYTES + off_, Al + ga_);                 \
        cp_async16(sbase_ + 2 * TILE_BYTES + off_, Bh + gb_);                 \
        cp_async16(sbase_ + 3 * TILE_BYTES + off_, Bl + gb_);                 \
    }                                                                         \
    cp_commit();                                                              \
} while (0)

    const int NT = K / BK;
    LOAD_STAGE(0, 0);

    for (int kt = 0; kt < NT; kt++) {
        if (kt + 1 < NT) {
            LOAD_STAGE((kt + 1) & 1, kt + 1);
            asm volatile("cp.async.wait_group 1;" ::: "memory");
        } else {
            asm volatile("cp.async.wait_group 0;" ::: "memory");
        }
        __syncthreads();

        const uint32_t sbase = su + (uint32_t)(kt & 1) * STAGE_BYTES;
        #pragma unroll
        for (int ks = 0; ks < 2; ks++) {
            uint32_t ah[2][4], al[2][4], bh[8][2], bl[8][2];
            #pragma unroll
            for (int i = 0; i < 2; i++) {
                const int r   = warp_m * 32 + i * 16 + (lane & 15);
                const int col = ks * 16 + (lane >> 4) * 8;
                const uint32_t ad = sbase + (uint32_t)(r * TSTRIDE + col) * 2;
                ldsm4(ad,              ah[i][0], ah[i][1], ah[i][2], ah[i][3]);
                ldsm4(ad + TILE_BYTES, al[i][0], al[i][1], al[i][2], al[i][3]);
            }
            #pragma unroll
            for (int p = 0; p < 4; p++) {
                const int g  = lane >> 3, i8 = lane & 7;
                const int n   = warp_n * 64 + p * 16 + ((g >> 1) << 3) + i8;
                const int col = ks * 16 + (g & 1) * 8;
                const uint32_t bd = sbase + 2 * TILE_BYTES +
                                    (uint32_t)(n * TSTRIDE + col) * 2;
                ldsm4(bd,              bh[2*p][0], bh[2*p][1], bh[2*p+1][0], bh[2*p+1][1]);
                ldsm4(bd + TILE_BYTES, bl[2*p][0], bl[2*p][1], bl[2*p+1][0], bl[2*p+1][1]);
            }
            #pragma unroll
            for (int i = 0; i < 2; i++)
                #pragma unroll
                for (int j = 0; j < 8; j++) {
                    hmma(acc[i][j], ah[i], bh[j]);
                    hmma(acc[i][j], ah[i], bl[j]);
                    hmma(acc[i][j], al[i], bh[j]);
                }
        }
        __syncthreads();
    }
#undef LOAD_STAGE

    // ---- epilogue ----
    const int tq = lane >> 2, tr = lane & 3;
    const float gam = (MODE == 3) ? gpt[0] : 0.0f;
    #pragma unroll
    for (int i = 0; i < 2; i++) {
        #pragma unroll
        for (int h2 = 0; h2 < 2; h2++) {
            const int row = bm0 + warp_m * 32 + i * 16 + tq + h2 * 8;
            const float bm_ = (MODE == 0) ? P.bias[z][row] : 0.0f;
            #pragma unroll
            for (int j = 0; j < 8; j++) {
                const int col = bn0 + warp_n * 64 + j * 8 + tr * 2;
                float v0 = acc[i][j][h2 * 2 + 0];
                float v1 = acc[i][j][h2 * 2 + 1];
                const size_t idx = (size_t)row * N + col;
                if (MODE == 0 || MODE == 1) {
                    v0 += (MODE == 0) ? bm_ : P.bias[z][col];
                    v1 += (MODE == 0) ? bm_ : P.bias[z][col + 1];
                    const __half h0 = __float2half_rn(v0);
                    const __half h1 = __float2half_rn(v1);
                    *reinterpret_cast<__half2*>(P.Ch[z] + idx) = __halves2half2(h0, h1);
                    *reinterpret_cast<__half2*>(P.Cl[z] + idx) =
                        __halves2half2(__float2half_rn(v0 - __half2float(h0)),
                                       __float2half_rn(v1 - __half2float(h1)));
                } else if (MODE == 2) {
                    *reinterpret_cast<float2*>(P.Cf[z] + idx) = make_float2(v0, v1);
                } else {
                    const float2 a2 = *reinterpret_cast<const float2*>(xf + idx);
                    const float2 b2 = *reinterpret_cast<const float2*>(xl + idx);
                    *reinterpret_cast<float2*>(P.Cf[z] + idx) =
                        make_float2(gam * v0 + 0.5f * (a2.x + b2.x),
                                    gam * v1 + 0.5f * (a2.y + b2.y));
                }
            }
        }
    }
}

// ---------------- transpose + fp16 split: x[1024,4096] -> xT[4096,1024] ----
__global__ __launch_bounds__(256)
void transpose_split(const float* __restrict__ x,
                     __half* __restrict__ th, __half* __restrict__ tl)
{
    __shared__ float t[32][33];
    const int tx = threadIdx.x & 31, ty = threadIdx.x >> 5;
    const int c0 = blockIdx.x * 32;
    const int r0 = blockIdx.y * 32;
    #pragma unroll
    for (int i = 0; i < 4; i++)
        t[ty + i * 8][tx] = x[(size_t)(r0 + ty + i * 8) * HW + c0 + tx];
    __syncthreads();
    #pragma unroll
    for (int i = 0; i < 4; i++) {
        const float v = t[tx][ty + i * 8];
        const size_t idx = (size_t)(c0 + ty + i * 8) * C_FULL + r0 + tx;
        const __half h = __float2half_rn(v);
        th[idx] = h;
        tl[idx] = __float2half_rn(v - __half2float(h));
    }
}

// ---------------- elementwise fp16 split (weights) --------------------------
__global__ __launch_bounds__(256)
void split_kernel(const float* __restrict__ x,
                  __half* __restrict__ h, __half* __restrict__ l, int n)
{
    const int i = blockIdx.x * 256 + threadIdx.x;
    if (i < n) {
        const float v = x[i];
        const __half hh = __float2half_rn(v);
        h[i] = hh;
        l[i] = __float2half_rn(v - __half2float(hh));
    }
}

// ---------------- fused dual softmax, split-fp16 output ---------------------
__global__ __launch_bounds__(256)
void softmax_sum_kernel(const float* __restrict__ LF, const float* __restrict__ LL,
                        __half* __restrict__ Sh, __half* __restrict__ Sl)
{
    const int row = blockIdx.x;
    const int tid = threadIdx.x;
    __shared__ float red[256];

    const float* pf = LF + (size_t)row * 1024;
    const float* pl = LL + (size_t)row * 1024;

    float vf[4], vl[4];
    #pragma unroll
    for (int k = 0; k < 4; k++) { vf[k] = pf[tid + 256 * k]; vl[k] = pl[tid + 256 * k]; }

    float m = fmaxf(fmaxf(vf[0], vf[1]), fmaxf(vf[2], vf[3]));
    red[tid] = m; __syncthreads();
    for (int s = 128; s > 0; s >>= 1) { if (tid < s) red[tid] = fmaxf(red[tid], red[tid + s]); __syncthreads(); }
    const float Mf = red[0]; __syncthreads();

    float ef[4], sf = 0.0f;
    #pragma unroll
    for (int k = 0; k < 4; k++) { ef[k] = expf(vf[k] - Mf); sf += ef[k]; }
    red[tid] = sf; __syncthreads();
    for (int s = 128; s > 0; s >>= 1) { if (tid < s) red[tid] += red[tid + s]; __syncthreads(); }
    const float Sf = red[0]; __syncthreads();

    m = fmaxf(fmaxf(vl[0], vl[1]), fmaxf(vl[2], vl[3]));
    red[tid] = m; __syncthreads();
    for (int s = 128; s > 0; s >>= 1) { if (tid < s) red[tid] = fmaxf(red[tid], red[tid + s]); __syncthreads(); }
    const float Ml = red[0]; __syncthreads();

    float el[4], sl = 0.0f;
    #pragma unroll
    for (int k = 0; k < 4; k++) { el[k] = expf(vl[k] - Ml); sl += el[k]; }
    red[tid] = sl; __syncthreads();
    for (int s = 128; s > 0; s >>= 1) { if (tid < s) red[tid] += red[tid + s]; __syncthreads(); }
    const float Sl_ = red[0];

    const float invf = 1.0f / Sf, invl = 1.0f / Sl_;
    #pragma unroll
    for (int k = 0; k < 4; k++) {
        const float v = ef[k] * invf + el[k] * invl;
        const size_t idx = (size_t)row * 1024 + tid + 256 * k;
        const __half h = __float2half_rn(v);
        Sh[idx] = h;
        Sl[idx] = __float2half_rn(v - __half2float(h));
    }
}

// ---------------------------------------------------------------------------
extern "C" void kernel_launch(void* const* d_in, const int* in_sizes, int n_in,
                              void* d_out, int out_size)
{
    (void)in_sizes; (void)n_in; (void)out_size;
    const float* x_f   = (const float*)d_in[0];
    const float* x_m   = (const float*)d_in[1];
    const float* x_l   = (const float*)d_in[2];
    const float* Wq    = (const float*)d_in[3];
    const float* bq    = (const float*)d_in[4];
    const float* Wk1   = (const float*)d_in[5];
    const float* bk1   = (const float*)d_in[6];
    const float* Wk2   = (const float*)d_in[7];
    const float* bk2   = (const float*)d_in[8];
    const float* Wv    = (const float*)d_in[9];
    const float* bv    = (const float*)d_in[10];
    const float* gamma = (const float*)d_in[11];
    float* out = (float*)d_out;

    __half *xTm_h, *xTm_l, *xTf_h, *xTf_l, *xTl_h, *xTl_l;
    __half *wq_h, *wq_l, *wk1_h, *wk1_l, *wk2_h, *wk2_l, *wv_h, *wv_l;
    __half *q_h, *q_l, *kf_h, *kf_l, *kl_h, *kl_l, *vT_h, *vT_l, *s_h, *s_l;
    float *lf, *ll;
    cudaGetSymbolAddress((void**)&xTm_h, g_xTm_h); cudaGetSymbolAddress((void**)&xTm_l, g_xTm_l);
    cudaGetSymbolAddress((void**)&xTf_h, g_xTf_h); cudaGetSymbolAddress((void**)&xTf_l, g_xTf_l);
    cudaGetSymbolAddress((void**)&xTl_h, g_xTl_h); cudaGetSymbolAddress((void**)&xTl_l, g_xTl_l);
    cudaGetSymbolAddress((void**)&wq_h,  g_Wq_h);  cudaGetSymbolAddress((void**)&wq_l,  g_Wq_l);
    cudaGetSymbolAddress((void**)&wk1_h, g_Wk1_h); cudaGetSymbolAddress((void**)&wk1_l, g_Wk1_l);
    cudaGetSymbolAddress((void**)&wk2_h, g_Wk2_h); cudaGetSymbolAddress((void**)&wk2_l, g_Wk2_l);
    cudaGetSymbolAddress((void**)&wv_h,  g_Wv_h);  cudaGetSymbolAddress((void**)&wv_l,  g_Wv_l);
    cudaGetSymbolAddress((void**)&q_h,  g_q_h);  cudaGetSymbolAddress((void**)&q_l,  g_q_l);
    cudaGetSymbolAddress((void**)&kf_h, g_kf_h); cudaGetSymbolAddress((void**)&kf_l, g_kf_l);
    cudaGetSymbolAddress((void**)&kl_h, g_kl_h); cudaGetSymbolAddress((void**)&kl_l, g_kl_l);
    cudaGetSymbolAddress((void**)&vT_h, g_vT_h); cudaGetSymbolAddress((void**)&vT_l, g_vT_l);
    cudaGetSymbolAddress((void**)&s_h,  g_S_h);  cudaGetSymbolAddress((void**)&s_l,  g_S_l);
    cudaGetSymbolAddress((void**)&lf, g_lf);     cudaGetSymbolAddress((void**)&ll, g_ll);

    cudaFuncSetAttribute(mma_gemm<0>, cudaFuncAttributeMaxDynamicSharedMemorySize, GEMM_SMEM);
    cudaFuncSetAttribute(mma_gemm<1>, cudaFuncAttributeMaxDynamicSharedMemorySize, GEMM_SMEM);
    cudaFuncSetAttribute(mma_gemm<2>, cudaFuncAttributeMaxDynamicSharedMemorySize, GEMM_SMEM);
    cudaFuncSetAttribute(mma_gemm<3>, cudaFuncAttributeMaxDynamicSharedMemorySize, GEMM_SMEM);

    // 1) weight splits
    split_kernel<<<(C_HALF * C_FULL) / 256, 256>>>(Wq,  wq_h,  wq_l,  C_HALF * C_FULL);
    split_kernel<<<(C_HALF * C_FULL) / 256, 256>>>(Wk1, wk1_h, wk1_l, C_HALF * C_FULL);
    split_kernel<<<(C_HALF * C_FULL) / 256, 256>>>(Wk2, wk2_h, wk2_l, C_HALF * C_FULL);
    split_kernel<<<(C_FULL * C_FULL) / 256, 256>>>(Wv,  wv_h,  wv_l,  C_FULL * C_FULL);

    // 2) transpose+split activations -> xT [4096,1024]
    dim3 tgrid(HW / 32, C_FULL / 32);
    transpose_split<<<tgrid, 256>>>(x_m, xTm_h, xTm_l);
    transpose_split<<<tgrid, 256>>>(x_f, xTf_h, xTf_l);
    transpose_split<<<tgrid, 256>>>(x_l, xTl_h, xTl_l);

    // 3) convs q/kf/kl batched over z: D = W @ xT^T + b[m]
    {
        GemmBatch P = {};
        P.Ah[0] = wq_h;  P.Al[0] = wq_l;  P.Bh[0] = xTm_h; P.Bl[0] = xTm_l;
        P.Ch[0] = q_h;   P.Cl[0] = q_l;   P.bias[0] = bq;
        P.Ah[1] = wk1_h; P.Al[1] = wk1_l; P.Bh[1] = xTf_h; P.Bl[1] = xTf_l;
        P.Ch[1] = kf_h;  P.Cl[1] = kf_l;  P.bias[1] = bk1;
        P.Ah[2] = wk2_h; P.Al[2] = wk2_l; P.Bh[2] = xTl_h; P.Bl[2] = xTl_l;
        P.Ch[2] = kl_h;  P.Cl[2] = kl_l;  P.bias[2] = bk2;
        mma_gemm<0><<<dim3(HW / BN, C_HALF / BM, 3), 256, GEMM_SMEM>>>(
            P, C_HALF, HW, C_FULL, nullptr, nullptr, nullptr);
    }

    // 4) vT = xT_m @ Wv^T + bv[n]
    {
        GemmBatch P = {};
        P.Ah[0] = xTm_h; P.Al[0] = xTm_l; P.Bh[0] = wv_h; P.Bl[0] = wv_l;
        P.Ch[0] = vT_h;  P.Cl[0] = vT_l;  P.bias[0] = bv;
        mma_gemm<1><<<dim3(C_FULL / BN, HW / BM, 1), 256, GEMM_SMEM>>>(
            P, HW, C_FULL, C_FULL, nullptr, nullptr, nullptr);
    }

    // 5) logits batched over z: [1024,2048] @ [1024,2048]^T
    {
        GemmBatch P = {};
        P.Ah[0] = kf_h; P.Al[0] = kf_l; P.Bh[0] = q_h; P.Bl[0] = q_l; P.Cf[0] = lf;
        P.Ah[1] = kl_h; P.Al[1] = kl_l; P.Bh[1] = q_h; P.Bl[1] = q_l; P.Cf[1] = ll;
        mma_gemm<2><<<dim3(C_FULL / BN, C_FULL / BM, 2), 256, GEMM_SMEM>>>(
            P, C_FULL, C_FULL, KLOG, nullptr, nullptr, nullptr);
    }

    // 6) S = softmax(lf) + softmax(ll)
    softmax_sum_kernel<<<C_FULL, 256>>>(lf, ll, s_h, s_l);

    // 7) out = gamma * (S @ vT^T) + 0.5*(x_f + x_l)
    {
        GemmBatch P = {};
        P.Ah[0] = s_h; P.Al[0] = s_l; P.Bh[0] = vT_h; P.Bl[0] = vT_l; P.Cf[0] = out;
        mma_gemm<3><<<dim3(HW / BN, C_FULL / BM, 1), 256, GEMM_SMEM>>>(
            P, C_FULL, HW, C_FULL, x_f, x_l, gamma);
    }
}